// round 5
// baseline (speedup 1.0000x reference)
#include <cuda_runtime.h>
#include <stdint.h>

// ---------------------------------------------------------------------------
// OneHopGCNNormNodeLabelAggregator — CSR-by-destination + warp-per-node gather.
//   deg[i]   = 1 + #{e : row[e]==i}
//   out[c,:] = rsqrt(deg[c])^2 * x[c,:]
//            + sum_{e: col[e]==c} rsqrt(deg[row[e]])*rsqrt(deg[c]) * x[row[e],:]
// x [100000,64] f32, edge_index [2,1600000] int32-or-int64 (runtime detect),
// out [100000,64] f32. No floating-point atomics anywhere.
//
// Pipeline (5 kernels): init -> count(col only) -> chained scan -> scatter
// (also counts deg over rows) -> warp-per-node aggregate (inline rsqrt).
// ---------------------------------------------------------------------------

#define MAX_NODES 131072
#define MAX_EDGES 1700000
#define FEAT 64
#define FEAT2 32
#define SCAN_TPB 512
#define SCAN_PER_BLOCK (SCAN_TPB * 4)   // 2048 per block
#define MAX_SCAN_BLOCKS 128

__device__ int g_is64;
__device__ int g_deg[MAX_NODES];       // row-degree incl. self loop
__device__ int g_cnt[MAX_NODES];       // in-count per col
__device__ int g_off[MAX_NODES + 1];   // exclusive scan of g_cnt
__device__ int g_cur[MAX_NODES];       // scatter cursors (init = g_off)
__device__ int g_flag[MAX_SCAN_BLOCKS];
__device__ int g_incl[MAX_SCAN_BLOCKS];
__device__ int g_src[MAX_EDGES];       // CSR payload: source per incoming edge

// --- init counters + scan flags + dtype detection -----------------------------
__global__ void k_init(const void* ei, int n) {
    int i = blockIdx.x * blockDim.x + threadIdx.x;
    if (i < n) {
        g_deg[i] = 1;   // self loop
        g_cnt[i] = 0;
    }
    if (i < MAX_SCAN_BLOCKS) g_flag[i] = 0;
    if (i == 0) {
        const long long* p = (const long long*)ei;
        int ok = 1;
#pragma unroll
        for (int k = 0; k < 16; k++) {
            long long v = p[k];
            if (v < 0 || v >= (long long)n) ok = 0;
        }
        g_is64 = ok;
    }
}

// --- count in-degree over cols (4 edges / thread) ------------------------------
__global__ void k_count(const void* __restrict__ ei, int n_edges) {
    int t = blockIdx.x * blockDim.x + threadIdx.x;
    int e = t * 4;
    if (e >= n_edges) return;
    if (e + 4 <= n_edges) {
        if (g_is64) {
            const longlong2* c = (const longlong2*)((const long long*)ei + n_edges);
            longlong2 c0 = c[t * 2], c1 = c[t * 2 + 1];
            atomicAdd(&g_cnt[(int)c0.x], 1);
            atomicAdd(&g_cnt[(int)c0.y], 1);
            atomicAdd(&g_cnt[(int)c1.x], 1);
            atomicAdd(&g_cnt[(int)c1.y], 1);
        } else {
            const int4* c = (const int4*)((const int*)ei + n_edges);
            int4 cv = c[t];
            atomicAdd(&g_cnt[cv.x], 1);
            atomicAdd(&g_cnt[cv.y], 1);
            atomicAdd(&g_cnt[cv.z], 1);
            atomicAdd(&g_cnt[cv.w], 1);
        }
    } else {
        int is64 = g_is64;
        for (int k = e; k < n_edges; k++) {
            int c = is64 ? (int)((const long long*)ei)[n_edges + k]
                         : ((const int*)ei)[n_edges + k];
            atomicAdd(&g_cnt[c], 1);
        }
    }
}

// --- single-kernel chained exclusive scan; writes g_off and g_cur ----------------
__global__ void k_scan(int n) {
    __shared__ int warp_sums[SCAN_TPB / 32];
    __shared__ int s_prev;
    const int NW = SCAN_TPB / 32;
    int tid = threadIdx.x, lane = tid & 31, wid = tid >> 5;
    int b = blockIdx.x;
    int idx = b * SCAN_PER_BLOCK + tid * 4;

    int v[4];
    int s = 0;
#pragma unroll
    for (int k = 0; k < 4; k++) {
        v[k] = (idx + k < n) ? g_cnt[idx + k] : 0;
        s += v[k];
    }
    int xs = s;
#pragma unroll
    for (int d = 1; d < 32; d <<= 1) {
        int y = __shfl_up_sync(0xFFFFFFFFu, xs, d);
        if (lane >= d) xs += y;
    }
    if (lane == 31) warp_sums[wid] = xs;
    __syncthreads();
    if (wid == 0) {
        int w = (lane < NW) ? warp_sums[lane] : 0;
#pragma unroll
        for (int d = 1; d < 32; d <<= 1) {
            int y = __shfl_up_sync(0xFFFFFFFFu, w, d);
            if (lane >= d) w += y;
        }
        if (lane < NW) warp_sums[lane] = w;
    }
    __syncthreads();
    int block_total = warp_sums[NW - 1];

    // chained block-prefix propagation (all blocks resident: 49 <= 148 SMs)
    if (tid == 0) {
        int prev = 0;
        if (b > 0) {
            while (atomicAdd(&g_flag[b - 1], 0) == 0) { }
            prev = g_incl[b - 1];
        }
        g_incl[b] = prev + block_total;
        __threadfence();
        atomicExch(&g_flag[b], 1);
        s_prev = prev;
    }
    __syncthreads();
    int base = s_prev;
    int warp_excl = (wid == 0) ? 0 : warp_sums[wid - 1];
    int te = base + warp_excl + (xs - s);
#pragma unroll
    for (int k = 0; k < 4; k++) {
        if (idx + k < n) {
            g_off[idx + k] = te;
            g_cur[idx + k] = te;
        }
        te += v[k];
    }
    if (tid == 0 && idx + SCAN_PER_BLOCK >= n + (tid * 4)) { /* noop */ }
    if (b == gridDim.x - 1 && tid == 0) g_off[n] = base + block_total;
}

// --- bucket-scatter sources by destination; also counts row-degree ---------------
__global__ void k_scatter(const void* __restrict__ ei, int n_edges) {
    int t = blockIdx.x * blockDim.x + threadIdx.x;
    int e = t * 4;
    if (e >= n_edges) return;
    int r[4], c[4], cnt4 = 4;
    if (e + 4 <= n_edges) {
        if (g_is64) {
            const longlong2* rp = (const longlong2*)ei;
            const longlong2* cp = (const longlong2*)((const long long*)ei + n_edges);
            longlong2 r0 = rp[t * 2], r1 = rp[t * 2 + 1];
            longlong2 c0 = cp[t * 2], c1 = cp[t * 2 + 1];
            r[0] = (int)r0.x; r[1] = (int)r0.y; r[2] = (int)r1.x; r[3] = (int)r1.y;
            c[0] = (int)c0.x; c[1] = (int)c0.y; c[2] = (int)c1.x; c[3] = (int)c1.y;
        } else {
            const int4* rp = (const int4*)ei;
            const int4* cp = (const int4*)((const int*)ei + n_edges);
            int4 rv = rp[t], cv = cp[t];
            r[0] = rv.x; r[1] = rv.y; r[2] = rv.z; r[3] = rv.w;
            c[0] = cv.x; c[1] = cv.y; c[2] = cv.z; c[3] = cv.w;
        }
    } else {
        int is64 = g_is64;
        cnt4 = n_edges - e;
        for (int k = 0; k < cnt4; k++) {
            r[k] = is64 ? (int)((const long long*)ei)[e + k]
                        : ((const int*)ei)[e + k];
            c[k] = is64 ? (int)((const long long*)ei)[n_edges + e + k]
                        : ((const int*)ei)[n_edges + e + k];
        }
    }
#pragma unroll
    for (int k = 0; k < 4; k++) {
        if (k < cnt4) {
            atomicAdd(&g_deg[r[k]], 1);
            int pos = atomicAdd(&g_cur[c[k]], 1);
            g_src[pos] = r[k];
        }
    }
}

// --- warp-per-node aggregation, 4x unrolled, inline rsqrt -------------------------
__global__ void k_agg(const float2* __restrict__ x, float2* __restrict__ out, int n) {
    int warp = (blockIdx.x * blockDim.x + threadIdx.x) >> 5;
    int lane = threadIdx.x & 31;
    if (warp >= n) return;
    float dc = rsqrtf((float)g_deg[warp]);
    float2 xv = x[warp * FEAT2 + lane];
    float w0 = dc * dc;
    float ax = w0 * xv.x, ay = w0 * xv.y;
    float bx = 0.f, by = 0.f;
    int beg = g_off[warp], end = g_off[warp + 1];
    int j = beg;
    for (; j + 4 <= end; j += 4) {
        int r0 = g_src[j],     r1 = g_src[j + 1];
        int r2 = g_src[j + 2], r3 = g_src[j + 3];
        float wA = dc * rsqrtf((float)g_deg[r0]);
        float wB = dc * rsqrtf((float)g_deg[r1]);
        float wC = dc * rsqrtf((float)g_deg[r2]);
        float wD = dc * rsqrtf((float)g_deg[r3]);
        float2 v0 = x[r0 * FEAT2 + lane];
        float2 v1 = x[r1 * FEAT2 + lane];
        float2 v2 = x[r2 * FEAT2 + lane];
        float2 v3 = x[r3 * FEAT2 + lane];
        ax += wA * v0.x;  ay += wA * v0.y;
        bx += wB * v1.x;  by += wB * v1.y;
        ax += wC * v2.x;  ay += wC * v2.y;
        bx += wD * v3.x;  by += wD * v3.y;
    }
    for (; j < end; j++) {
        int r0 = g_src[j];
        float wA = dc * rsqrtf((float)g_deg[r0]);
        float2 v0 = x[r0 * FEAT2 + lane];
        ax += wA * v0.x;  ay += wA * v0.y;
    }
    out[warp * FEAT2 + lane] = make_float2(ax + bx, ay + by);
}

extern "C" void kernel_launch(void* const* d_in, const int* in_sizes, int n_in,
                              void* d_out, int out_size) {
    const float* x  = (const float*)d_in[0];
    const void*  ei = d_in[1];
    float* out = (float*)d_out;

    const int n       = in_sizes[0] / FEAT;   // 100000
    const int n_edges = in_sizes[1] / 2;      // 1600000
    const int TPB = 256;
    const int nscan = (n + SCAN_PER_BLOCK - 1) / SCAN_PER_BLOCK;   // 49
    const int nvec  = (n_edges + 3) / 4;

    k_init<<<(n + TPB - 1) / TPB, TPB>>>(ei, n);
    k_count<<<(nvec + TPB - 1) / TPB, TPB>>>(ei, n_edges);
    k_scan<<<nscan, SCAN_TPB>>>(n);
    k_scatter<<<(nvec + TPB - 1) / TPB, TPB>>>(ei, n_edges);

    long long agg_threads = (long long)n * 32;
    k_agg<<<(int)((agg_threads + TPB - 1) / TPB), TPB>>>(
        (const float2*)x, (float2*)out, n);
}

// round 6
// speedup vs baseline: 1.0440x; 1.0440x over previous
#include <cuda_runtime.h>
#include <stdint.h>

// ---------------------------------------------------------------------------
// OneHopGCNNormNodeLabelAggregator — CSR-by-destination + warp-per-node gather.
//   deg[i]   = 1 + #{e : row[e]==i}
//   dis[i]   = rsqrt(deg[i])
//   out[c,:] = dis[c]^2 * x[c,:] + sum_{e: col[e]==c} dis[row[e]]*dis[c]*x[row[e],:]
// x [100000,64] f32, edge_index [2,1600000] int32-or-int64 (runtime detect),
// out [100000,64] f32. No floating-point atomics anywhere.
//
// R6: 1 edge/thread for atomic passes (max MLP to hide ATOMG latency — R5's
// 4-edge/thread vectorization serialized the atomic chains and regressed 60%),
// single chained scan with fused dis computation, 4x-unrolled warp-per-node agg.
// ---------------------------------------------------------------------------

#define MAX_NODES 131072
#define MAX_EDGES 1700000
#define FEAT 64
#define FEAT2 32
#define SCAN_TPB 512
#define SCAN_PER_BLOCK (SCAN_TPB * 4)   // 2048 per block
#define MAX_SCAN_BLOCKS 128

__device__ int   g_is64;
__device__ int   g_deg[MAX_NODES];       // row-degree incl. self loop
__device__ int   g_cnt[MAX_NODES];       // in-count per col
__device__ int   g_off[MAX_NODES + 1];   // exclusive scan of g_cnt
__device__ int   g_cur[MAX_NODES];       // scatter cursors (init = g_off)
__device__ float g_dis[MAX_NODES];       // rsqrt(deg)
__device__ int   g_flag[MAX_SCAN_BLOCKS];
__device__ int   g_incl[MAX_SCAN_BLOCKS];
__device__ int   g_src[MAX_EDGES];       // CSR payload: source per incoming edge

__device__ __forceinline__ int load_idx(const void* ei, int part, int e,
                                        int n_edges, int is64) {
    if (is64) return (int)((const long long*)ei)[(long long)part * n_edges + e];
    return ((const int*)ei)[(long long)part * n_edges + e];
}

// --- init counters + scan flags + dtype detection -----------------------------
__global__ void k_init(const void* ei, int n) {
    int i = blockIdx.x * blockDim.x + threadIdx.x;
    if (i < n) {
        g_deg[i] = 1;   // self loop
        g_cnt[i] = 0;
    }
    if (i < MAX_SCAN_BLOCKS) g_flag[i] = 0;
    if (i == 0) {
        const long long* p = (const long long*)ei;
        int ok = 1;
#pragma unroll
        for (int k = 0; k < 16; k++) {
            long long v = p[k];
            if (v < 0 || v >= (long long)n) ok = 0;
        }
        g_is64 = ok;
    }
}

// --- per-edge counting: deg over rows, cnt over cols (1 edge / thread) ---------
__global__ void k_count(const void* __restrict__ ei, int n_edges) {
    int e = blockIdx.x * blockDim.x + threadIdx.x;
    if (e < n_edges) {
        int is64 = g_is64;
        atomicAdd(&g_deg[load_idx(ei, 0, e, n_edges, is64)], 1);
        atomicAdd(&g_cnt[load_idx(ei, 1, e, n_edges, is64)], 1);
    }
}

// --- single chained exclusive scan of g_cnt; fused dis; writes off + cur --------
__global__ void k_scan(int n) {
    __shared__ int warp_sums[SCAN_TPB / 32];
    __shared__ int s_prev;
    const int NW = SCAN_TPB / 32;
    int tid = threadIdx.x, lane = tid & 31, wid = tid >> 5;
    int b = blockIdx.x;
    int idx = b * SCAN_PER_BLOCK + tid * 4;

    int v[4];
    int s = 0;
#pragma unroll
    for (int k = 0; k < 4; k++) {
        if (idx + k < n) {
            v[k] = g_cnt[idx + k];
            g_dis[idx + k] = rsqrtf((float)g_deg[idx + k]);   // fused
        } else v[k] = 0;
        s += v[k];
    }
    int xs = s;
#pragma unroll
    for (int d = 1; d < 32; d <<= 1) {
        int y = __shfl_up_sync(0xFFFFFFFFu, xs, d);
        if (lane >= d) xs += y;
    }
    if (lane == 31) warp_sums[wid] = xs;
    __syncthreads();
    if (wid == 0) {
        int w = (lane < NW) ? warp_sums[lane] : 0;
#pragma unroll
        for (int d = 1; d < 32; d <<= 1) {
            int y = __shfl_up_sync(0xFFFFFFFFu, w, d);
            if (lane >= d) w += y;
        }
        if (lane < NW) warp_sums[lane] = w;
    }
    __syncthreads();
    int block_total = warp_sums[NW - 1];

    // chained block-prefix propagation (all 49 blocks resident on 148 SMs)
    if (tid == 0) {
        int prev = 0;
        if (b > 0) {
            while (atomicAdd(&g_flag[b - 1], 0) == 0) { }
            prev = g_incl[b - 1];
        }
        g_incl[b] = prev + block_total;
        __threadfence();
        atomicExch(&g_flag[b], 1);
        s_prev = prev;
    }
    __syncthreads();
    int base = s_prev;
    int warp_excl = (wid == 0) ? 0 : warp_sums[wid - 1];
    int te = base + warp_excl + (xs - s);
#pragma unroll
    for (int k = 0; k < 4; k++) {
        if (idx + k < n) {
            g_off[idx + k] = te;
            g_cur[idx + k] = te;
        }
        te += v[k];
    }
    if (b == gridDim.x - 1 && tid == 0) g_off[n] = base + block_total;
}

// --- bucket-scatter source ids by destination (1 edge / thread) -----------------
__global__ void k_scatter(const void* __restrict__ ei, int n_edges) {
    int e = blockIdx.x * blockDim.x + threadIdx.x;
    if (e < n_edges) {
        int is64 = g_is64;
        int r = load_idx(ei, 0, e, n_edges, is64);
        int c = load_idx(ei, 1, e, n_edges, is64);
        int pos = atomicAdd(&g_cur[c], 1);
        g_src[pos] = r;
    }
}

// --- warp-per-node aggregation, 4x unrolled, precomputed dis --------------------
__global__ void k_agg(const float2* __restrict__ x, float2* __restrict__ out, int n) {
    int warp = (blockIdx.x * blockDim.x + threadIdx.x) >> 5;
    int lane = threadIdx.x & 31;
    if (warp >= n) return;
    float dc = g_dis[warp];
    float2 xv = x[warp * FEAT2 + lane];
    float w0 = dc * dc;
    float ax = w0 * xv.x, ay = w0 * xv.y;
    float bx = 0.f, by = 0.f;
    int beg = g_off[warp], end = g_off[warp + 1];
    int j = beg;
    for (; j + 4 <= end; j += 4) {
        int r0 = g_src[j],     r1 = g_src[j + 1];
        int r2 = g_src[j + 2], r3 = g_src[j + 3];
        float wA = dc * g_dis[r0];
        float wB = dc * g_dis[r1];
        float wC = dc * g_dis[r2];
        float wD = dc * g_dis[r3];
        float2 v0 = x[r0 * FEAT2 + lane];
        float2 v1 = x[r1 * FEAT2 + lane];
        float2 v2 = x[r2 * FEAT2 + lane];
        float2 v3 = x[r3 * FEAT2 + lane];
        ax += wA * v0.x;  ay += wA * v0.y;
        bx += wB * v1.x;  by += wB * v1.y;
        ax += wC * v2.x;  ay += wC * v2.y;
        bx += wD * v3.x;  by += wD * v3.y;
    }
    for (; j < end; j++) {
        int r0 = g_src[j];
        float wA = dc * g_dis[r0];
        float2 v0 = x[r0 * FEAT2 + lane];
        ax += wA * v0.x;  ay += wA * v0.y;
    }
    out[warp * FEAT2 + lane] = make_float2(ax + bx, ay + by);
}

extern "C" void kernel_launch(void* const* d_in, const int* in_sizes, int n_in,
                              void* d_out, int out_size) {
    const float* x  = (const float*)d_in[0];
    const void*  ei = d_in[1];
    float* out = (float*)d_out;

    const int n       = in_sizes[0] / FEAT;   // 100000
    const int n_edges = in_sizes[1] / 2;      // 1600000
    const int TPB = 256;
    const int nscan = (n + SCAN_PER_BLOCK - 1) / SCAN_PER_BLOCK;   // 49

    k_init<<<(n + TPB - 1) / TPB, TPB>>>(ei, n);
    k_count<<<(n_edges + TPB - 1) / TPB, TPB>>>(ei, n_edges);
    k_scan<<<nscan, SCAN_TPB>>>(n);
    k_scatter<<<(n_edges + TPB - 1) / TPB, TPB>>>(ei, n_edges);

    long long agg_threads = (long long)n * 32;
    k_agg<<<(int)((agg_threads + TPB - 1) / TPB), TPB>>>(
        (const float2*)x, (float2*)out, n);
}

// round 7
// speedup vs baseline: 1.5047x; 1.4413x over previous
#include <cuda_runtime.h>
#include <stdint.h>

// ---------------------------------------------------------------------------
// OneHopGCNNormNodeLabelAggregator — CSR-by-destination + warp-per-node gather.
//   deg[i]   = 1 + #{e : row[e]==i}
//   out[c,:] = rsqrt(deg[c])^2 * x[c,:]
//            + sum_{e: col[e]==c} rsqrt(deg[row[e]])*rsqrt(deg[c]) * x[row[e],:]
// x [100000,64] f32, edge_index [2,1600000] int32-or-int64 (runtime detect),
// out [100000,64] f32. No floating-point atomics anywhere.
//
// R7: R4 structure (3-phase scan — the R6 chained spin-scan cost ~1us per
// serial block-to-block hop and regressed 47us). Count pass is col-only;
// row-degree counting rides in the scatter pass as an independent RED;
// rsqrt computed inline in agg (MUFU hidden under memory latency).
// All atomic passes: 1 edge/thread for maximum latency-hiding MLP.
// ---------------------------------------------------------------------------

#define MAX_NODES 131072
#define MAX_EDGES 1700000
#define FEAT 64
#define FEAT2 32
#define SCAN_TPB 512
#define SCAN_PER_BLOCK (SCAN_TPB * 4)   // 2048 elements per scan block
#define MAX_SCAN_BLOCKS 128

__device__ int g_is64;
__device__ int g_deg[MAX_NODES];       // row-degree incl. self loop
__device__ int g_cnt[MAX_NODES];       // in-count per col (excl. self loop)
__device__ int g_off[MAX_NODES + 1];   // exclusive scan of g_cnt
__device__ int g_cur[MAX_NODES];       // scatter cursors (init = g_off)
__device__ int g_bsum[MAX_SCAN_BLOCKS + 1];
__device__ int g_src[MAX_EDGES];       // CSR payload: source per incoming edge

__device__ __forceinline__ int load_idx(const void* ei, int part, int e,
                                        int n_edges, int is64) {
    if (is64) return (int)((const long long*)ei)[(long long)part * n_edges + e];
    return ((const int*)ei)[(long long)part * n_edges + e];
}

// --- init counters + dtype detection -----------------------------------------
__global__ void k_init(const void* ei, int n) {
    int i = blockIdx.x * blockDim.x + threadIdx.x;
    if (i < n) {
        g_deg[i] = 1;   // self loop
        g_cnt[i] = 0;
    }
    if (i == 0) {
        const long long* p = (const long long*)ei;
        int ok = 1;
#pragma unroll
        for (int k = 0; k < 16; k++) {
            long long v = p[k];
            if (v < 0 || v >= (long long)n) ok = 0;
        }
        g_is64 = ok;
    }
}

// --- count in-degree over cols ONLY (1 edge / thread) --------------------------
__global__ void k_count(const void* __restrict__ ei, int n_edges) {
    int e = blockIdx.x * blockDim.x + threadIdx.x;
    if (e < n_edges) {
        atomicAdd(&g_cnt[load_idx(ei, 1, e, n_edges, g_is64)], 1);
    }
}

// --- scan phase A: per-block sums of g_cnt -------------------------------------
__global__ void k_scanA(int n) {
    __shared__ int warp_sums[SCAN_TPB / 32];
    int tid = threadIdx.x, lane = tid & 31, wid = tid >> 5;
    int base = blockIdx.x * SCAN_PER_BLOCK;
    int s = 0;
#pragma unroll
    for (int k = 0; k < 4; k++) {
        int idx = base + tid + k * SCAN_TPB;
        if (idx < n) s += g_cnt[idx];
    }
#pragma unroll
    for (int d = 16; d > 0; d >>= 1) s += __shfl_down_sync(0xFFFFFFFFu, s, d);
    if (lane == 0) warp_sums[wid] = s;
    __syncthreads();
    if (wid == 0) {
        int v = (lane < SCAN_TPB / 32) ? warp_sums[lane] : 0;
#pragma unroll
        for (int d = 16; d > 0; d >>= 1) v += __shfl_down_sync(0xFFFFFFFFu, v, d);
        if (lane == 0) g_bsum[blockIdx.x] = v;
    }
}

// --- scan phase B: exclusive scan of block sums (one small block) ---------------
__global__ void k_scanB(int nblocks, int n) {
    int tid = threadIdx.x, lane = tid & 31, wid = tid >> 5;
    __shared__ int ws[4];
    int v = (tid < nblocks) ? g_bsum[tid] : 0;
    int xs = v;
#pragma unroll
    for (int d = 1; d < 32; d <<= 1) {
        int y = __shfl_up_sync(0xFFFFFFFFu, xs, d);
        if (lane >= d) xs += y;
    }
    if (lane == 31) ws[wid] = xs;
    __syncthreads();
    int carry = 0;
#pragma unroll
    for (int w = 0; w < 4; w++) {
        if (w < wid) carry += ws[w];
    }
    int excl = carry + xs - v;
    if (tid < nblocks) g_bsum[tid] = excl;
    if (tid == nblocks - 1) {
        g_bsum[nblocks] = excl + v;
        g_off[n] = excl + v;   // total edge count
    }
}

// --- scan phase C: block-local exclusive scan + offset; init cursors ------------
__global__ void k_scanC(int n) {
    __shared__ int warp_sums[SCAN_TPB / 32];
    int tid = threadIdx.x, lane = tid & 31, wid = tid >> 5;
    int base = blockIdx.x * SCAN_PER_BLOCK;
    int idx = base + tid * 4;                  // contiguous 4 per thread
    int v[4];
    int s = 0;
#pragma unroll
    for (int k = 0; k < 4; k++) {
        v[k] = (idx + k < n) ? g_cnt[idx + k] : 0;
        s += v[k];
    }
    int xs = s;
#pragma unroll
    for (int d = 1; d < 32; d <<= 1) {
        int y = __shfl_up_sync(0xFFFFFFFFu, xs, d);
        if (lane >= d) xs += y;
    }
    if (lane == 31) warp_sums[wid] = xs;
    __syncthreads();
    if (wid == 0) {
        int w = (lane < SCAN_TPB / 32) ? warp_sums[lane] : 0;
#pragma unroll
        for (int d = 1; d < 32; d <<= 1) {
            int y = __shfl_up_sync(0xFFFFFFFFu, w, d);
            if (lane >= d) w += y;
        }
        if (lane < SCAN_TPB / 32) warp_sums[lane] = w;
    }
    __syncthreads();
    int warp_excl = (wid == 0) ? 0 : warp_sums[wid - 1];
    int te = g_bsum[blockIdx.x] + warp_excl + (xs - s);
#pragma unroll
    for (int k = 0; k < 4; k++) {
        if (idx + k < n) {
            g_off[idx + k] = te;
            g_cur[idx + k] = te;   // cursor starts at segment base
        }
        te += v[k];
    }
}

// --- bucket-scatter sources by destination; also count row-degree ----------------
// 1 edge/thread: the cursor ATOMG and the deg RED are independent per thread,
// so 1.6M threads give maximal memory-level parallelism to hide atomic latency.
__global__ void k_scatter(const void* __restrict__ ei, int n_edges) {
    int e = blockIdx.x * blockDim.x + threadIdx.x;
    if (e < n_edges) {
        int is64 = g_is64;
        int r = load_idx(ei, 0, e, n_edges, is64);
        int c = load_idx(ei, 1, e, n_edges, is64);
        atomicAdd(&g_deg[r], 1);               // RED, no return — independent
        int pos = atomicAdd(&g_cur[c], 1);     // ATOMG with return
        g_src[pos] = r;
    }
}

// --- warp-per-node aggregation, 2x unrolled, inline rsqrt ------------------------
__global__ void k_agg(const float2* __restrict__ x, float2* __restrict__ out, int n) {
    int warp = (blockIdx.x * blockDim.x + threadIdx.x) >> 5;
    int lane = threadIdx.x & 31;
    if (warp >= n) return;
    float dc = rsqrtf((float)g_deg[warp]);
    float2 xv = x[warp * FEAT2 + lane];
    float w0 = dc * dc;
    float ax = w0 * xv.x, ay = w0 * xv.y;
    float bx = 0.f, by = 0.f;
    int beg = g_off[warp], end = g_off[warp + 1];
    int j = beg;
    for (; j + 2 <= end; j += 2) {
        int r0 = g_src[j];
        int r1 = g_src[j + 1];
        float wA = dc * rsqrtf((float)g_deg[r0]);
        float wB = dc * rsqrtf((float)g_deg[r1]);
        float2 v0 = x[r0 * FEAT2 + lane];
        float2 v1 = x[r1 * FEAT2 + lane];
        ax += wA * v0.x;  ay += wA * v0.y;
        bx += wB * v1.x;  by += wB * v1.y;
    }
    if (j < end) {
        int r0 = g_src[j];
        float wA = dc * rsqrtf((float)g_deg[r0]);
        float2 v0 = x[r0 * FEAT2 + lane];
        ax += wA * v0.x;  ay += wA * v0.y;
    }
    out[warp * FEAT2 + lane] = make_float2(ax + bx, ay + by);
}

extern "C" void kernel_launch(void* const* d_in, const int* in_sizes, int n_in,
                              void* d_out, int out_size) {
    const float* x  = (const float*)d_in[0];
    const void*  ei = d_in[1];
    float* out = (float*)d_out;

    const int n       = in_sizes[0] / FEAT;   // 100000
    const int n_edges = in_sizes[1] / 2;      // 1600000
    const int TPB = 256;
    const int nscan = (n + SCAN_PER_BLOCK - 1) / SCAN_PER_BLOCK;   // 49

    k_init<<<(n + TPB - 1) / TPB, TPB>>>(ei, n);
    k_count<<<(n_edges + TPB - 1) / TPB, TPB>>>(ei, n_edges);
    k_scanA<<<nscan, SCAN_TPB>>>(n);
    k_scanB<<<1, 128>>>(nscan, n);
    k_scanC<<<nscan, SCAN_TPB>>>(n);
    k_scatter<<<(n_edges + TPB - 1) / TPB, TPB>>>(ei, n_edges);

    long long agg_threads = (long long)n * 32;
    k_agg<<<(int)((agg_threads + TPB - 1) / TPB), TPB>>>(
        (const float2*)x, (float2*)out, n);
}

// round 8
// speedup vs baseline: 1.6106x; 1.0704x over previous
#include <cuda_runtime.h>
#include <stdint.h>

// ---------------------------------------------------------------------------
// OneHopGCNNormNodeLabelAggregator — CSR-by-destination + warp-per-node gather.
//   deg[i]   = 1 + #{e : row[e]==i}
//   dis[i]   = rsqrt(deg[i])
//   out[c,:] = dis[c]^2 * x[c,:] + sum_{e: col[e]==c} dis[row[e]]*dis[c]*x[row[e],:]
// x [100000,64] f32, edge_index [2,1600000] int32-or-int64 (runtime detect),
// out [100000,64] f32. No floating-point atomics anywhere.
//
// R8 = R4 (87.1us champion: 1-edge/thread atomic passes, 3-phase scan with
// dis fused into scanA, precomputed g_dis in agg, x2-unrolled agg) with
// scanB folded into scanC: each scanC block redundantly prefix-sums the <=49
// block sums itself (L2-resident), saving the 4.4us grid=1 scanB launch.
// ---------------------------------------------------------------------------

#define MAX_NODES 131072
#define MAX_EDGES 1700000
#define FEAT 64
#define FEAT2 32
#define SCAN_TPB 512
#define SCAN_PER_BLOCK (SCAN_TPB * 4)   // 2048 elements per scan block
#define MAX_SCAN_BLOCKS 128

__device__ int   g_is64;
__device__ int   g_deg[MAX_NODES];       // row-degree incl. self loop
__device__ int   g_cnt[MAX_NODES];       // in-count per col (excl. self loop)
__device__ int   g_off[MAX_NODES + 1];   // exclusive scan of g_cnt
__device__ int   g_cur[MAX_NODES];       // scatter cursors (init = g_off)
__device__ float g_dis[MAX_NODES];       // rsqrt(deg)
__device__ int   g_bsum[MAX_SCAN_BLOCKS];
__device__ int   g_src[MAX_EDGES];       // CSR payload: source per incoming edge

__device__ __forceinline__ int load_idx(const void* ei, int part, int e,
                                        int n_edges, int is64) {
    if (is64) return (int)((const long long*)ei)[(long long)part * n_edges + e];
    return ((const int*)ei)[(long long)part * n_edges + e];
}

// --- init counters + dtype detection -----------------------------------------
__global__ void k_init(const void* ei, int n) {
    int i = blockIdx.x * blockDim.x + threadIdx.x;
    if (i < n) {
        g_deg[i] = 1;   // self loop
        g_cnt[i] = 0;
    }
    if (i == 0) {
        const long long* p = (const long long*)ei;
        int ok = 1;
#pragma unroll
        for (int k = 0; k < 16; k++) {
            long long v = p[k];
            if (v < 0 || v >= (long long)n) ok = 0;
        }
        g_is64 = ok;
    }
}

// --- per-edge counting: deg over rows + cnt over cols (1 edge / thread) --------
__global__ void k_count(const void* __restrict__ ei, int n_edges) {
    int e = blockIdx.x * blockDim.x + threadIdx.x;
    if (e < n_edges) {
        int is64 = g_is64;
        atomicAdd(&g_deg[load_idx(ei, 0, e, n_edges, is64)], 1);
        atomicAdd(&g_cnt[load_idx(ei, 1, e, n_edges, is64)], 1);
    }
}

// --- scan phase A: per-block sums of g_cnt; fused g_dis computation -------------
__global__ void k_scanA(int n) {
    __shared__ int warp_sums[SCAN_TPB / 32];
    int tid = threadIdx.x, lane = tid & 31, wid = tid >> 5;
    int base = blockIdx.x * SCAN_PER_BLOCK;
    int s = 0;
#pragma unroll
    for (int k = 0; k < 4; k++) {
        int idx = base + tid + k * SCAN_TPB;
        if (idx < n) {
            s += g_cnt[idx];
            g_dis[idx] = rsqrtf((float)g_deg[idx]);   // fused elementwise pass
        }
    }
#pragma unroll
    for (int d = 16; d > 0; d >>= 1) s += __shfl_down_sync(0xFFFFFFFFu, s, d);
    if (lane == 0) warp_sums[wid] = s;
    __syncthreads();
    if (wid == 0) {
        int v = (lane < SCAN_TPB / 32) ? warp_sums[lane] : 0;
#pragma unroll
        for (int d = 16; d > 0; d >>= 1) v += __shfl_down_sync(0xFFFFFFFFu, v, d);
        if (lane == 0) g_bsum[blockIdx.x] = v;
    }
}

// --- scan phase C: block prefix (computed in-block over <=49 sums) +
//     block-local exclusive scan; writes g_off and g_cur ------------------------
__global__ void k_scanC(int n) {
    __shared__ int warp_sums[SCAN_TPB / 32];
    __shared__ int s_base;
    int tid = threadIdx.x, lane = tid & 31, wid = tid >> 5;
    int b = blockIdx.x;
    int nblocks = gridDim.x;

    // warp 0: exclusive prefix of block sums up to (and excluding) block b,
    // plus total for the final g_off[n] write. <=128 block sums, 4 per lane.
    if (wid == 0) {
        int p = 0, tot = 0;
#pragma unroll
        for (int k = 0; k < 4; k++) {
            int i = lane + k * 32;
            if (i < nblocks) {
                int v = g_bsum[i];
                tot += v;
                if (i < b) p += v;
            }
        }
#pragma unroll
        for (int d = 16; d > 0; d >>= 1) {
            p   += __shfl_down_sync(0xFFFFFFFFu, p, d);
            tot += __shfl_down_sync(0xFFFFFFFFu, tot, d);
        }
        if (lane == 0) {
            s_base = p;
            if (b == nblocks - 1) g_off[n] = tot;   // total edge count
        }
    }

    int base = b * SCAN_PER_BLOCK;
    int idx = base + tid * 4;                  // contiguous 4 per thread
    int v[4];
    int s = 0;
#pragma unroll
    for (int k = 0; k < 4; k++) {
        v[k] = (idx + k < n) ? g_cnt[idx + k] : 0;
        s += v[k];
    }
    int xs = s;
#pragma unroll
    for (int d = 1; d < 32; d <<= 1) {
        int y = __shfl_up_sync(0xFFFFFFFFu, xs, d);
        if (lane >= d) xs += y;
    }
    if (lane == 31) warp_sums[wid] = xs;
    __syncthreads();
    if (wid == 0) {
        int w = (lane < SCAN_TPB / 32) ? warp_sums[lane] : 0;
#pragma unroll
        for (int d = 1; d < 32; d <<= 1) {
            int y = __shfl_up_sync(0xFFFFFFFFu, w, d);
            if (lane >= d) w += y;
        }
        if (lane < SCAN_TPB / 32) warp_sums[lane] = w;
    }
    __syncthreads();
    int warp_excl = (wid == 0) ? 0 : warp_sums[wid - 1];
    int te = s_base + warp_excl + (xs - s);
#pragma unroll
    for (int k = 0; k < 4; k++) {
        if (idx + k < n) {
            g_off[idx + k] = te;
            g_cur[idx + k] = te;   // cursor starts at segment base
        }
        te += v[k];
    }
}

// --- bucket-scatter source ids by destination (1 edge / thread) -----------------
__global__ void k_scatter(const void* __restrict__ ei, int n_edges) {
    int e = blockIdx.x * blockDim.x + threadIdx.x;
    if (e < n_edges) {
        int is64 = g_is64;
        int r = load_idx(ei, 0, e, n_edges, is64);
        int c = load_idx(ei, 1, e, n_edges, is64);
        int pos = atomicAdd(&g_cur[c], 1);
        g_src[pos] = r;
    }
}

// --- warp-per-node aggregation, 2x unrolled, precomputed dis --------------------
__global__ void k_agg(const float2* __restrict__ x, float2* __restrict__ out, int n) {
    int warp = (blockIdx.x * blockDim.x + threadIdx.x) >> 5;
    int lane = threadIdx.x & 31;
    if (warp >= n) return;
    float dc = g_dis[warp];
    float2 xv = x[warp * FEAT2 + lane];
    float w0 = dc * dc;                 // self-loop weight
    float ax = w0 * xv.x, ay = w0 * xv.y;
    float bx = 0.f, by = 0.f;
    int beg = g_off[warp], end = g_off[warp + 1];
    int j = beg;
    for (; j + 2 <= end; j += 2) {
        int r0 = g_src[j];
        int r1 = g_src[j + 1];
        float wA = dc * g_dis[r0];
        float wB = dc * g_dis[r1];
        float2 v0 = x[r0 * FEAT2 + lane];
        float2 v1 = x[r1 * FEAT2 + lane];
        ax += wA * v0.x;  ay += wA * v0.y;
        bx += wB * v1.x;  by += wB * v1.y;
    }
    if (j < end) {
        int r0 = g_src[j];
        float wA = dc * g_dis[r0];
        float2 v0 = x[r0 * FEAT2 + lane];
        ax += wA * v0.x;  ay += wA * v0.y;
    }
    out[warp * FEAT2 + lane] = make_float2(ax + bx, ay + by);
}

extern "C" void kernel_launch(void* const* d_in, const int* in_sizes, int n_in,
                              void* d_out, int out_size) {
    const float* x  = (const float*)d_in[0];
    const void*  ei = d_in[1];
    float* out = (float*)d_out;

    const int n       = in_sizes[0] / FEAT;   // 100000
    const int n_edges = in_sizes[1] / 2;      // 1600000
    const int TPB = 256;
    const int nscan = (n + SCAN_PER_BLOCK - 1) / SCAN_PER_BLOCK;   // 49

    k_init<<<(n + TPB - 1) / TPB, TPB>>>(ei, n);
    k_count<<<(n_edges + TPB - 1) / TPB, TPB>>>(ei, n_edges);
    k_scanA<<<nscan, SCAN_TPB>>>(n);
    k_scanC<<<nscan, SCAN_TPB>>>(n);
    k_scatter<<<(n_edges + TPB - 1) / TPB, TPB>>>(ei, n_edges);

    long long agg_threads = (long long)n * 32;
    k_agg<<<(int)((agg_threads + TPB - 1) / TPB), TPB>>>(
        (const float2*)x, (float2*)out, n);
}

// round 9
// speedup vs baseline: 1.6232x; 1.0078x over previous
#include <cuda_runtime.h>
#include <stdint.h>

// ---------------------------------------------------------------------------
// OneHopGCNNormNodeLabelAggregator — CSR-by-destination + warp-per-node gather.
//   deg[i]   = 1 + #{e : row[e]==i}
//   dis[i]   = rsqrt(deg[i])
//   out[c,:] = dis[c]^2 * x[c,:] + sum_{e: col[e]==c} dis[row[e]]*dis[c]*x[row[e],:]
// x [100000,64] f32, edge_index [2,1600000] int32-or-int64 (runtime detect),
// out [100000,64] f32. No floating-point atomics anywhere.
//
// R9: CSR payload carries (src, dis[src]) packed as uint2 — the random 32B-
// sector dis gather moves from byte-bound k_agg into atomic-ALU-bound
// k_scatter where bandwidth is free; agg streams 8B/edge sequentially.
// Scan uses 98 blocks (1024 elems each) for better SM coverage.
// ---------------------------------------------------------------------------

#define MAX_NODES 131072
#define MAX_EDGES 1700000
#define FEAT 64
#define FEAT2 32
#define SCAN_TPB 256
#define SCAN_PER_BLOCK (SCAN_TPB * 4)   // 1024 elements per scan block
#define MAX_SCAN_BLOCKS 128

__device__ int   g_is64;
__device__ int   g_deg[MAX_NODES];       // row-degree incl. self loop
__device__ int   g_cnt[MAX_NODES];       // in-count per col (excl. self loop)
__device__ int   g_off[MAX_NODES + 1];   // exclusive scan of g_cnt
__device__ int   g_cur[MAX_NODES];       // scatter cursors (init = g_off)
__device__ float g_dis[MAX_NODES];       // rsqrt(deg)
__device__ int   g_bsum[MAX_SCAN_BLOCKS];
__device__ uint2 g_srcw[MAX_EDGES];      // CSR payload: (src id, dis[src] bits)

__device__ __forceinline__ int load_idx(const void* ei, int part, int e,
                                        int n_edges, int is64) {
    if (is64) return (int)((const long long*)ei)[(long long)part * n_edges + e];
    return ((const int*)ei)[(long long)part * n_edges + e];
}

// --- init counters + dtype detection -----------------------------------------
__global__ void k_init(const void* ei, int n) {
    int i = blockIdx.x * blockDim.x + threadIdx.x;
    if (i < n) {
        g_deg[i] = 1;   // self loop
        g_cnt[i] = 0;
    }
    if (i == 0) {
        const long long* p = (const long long*)ei;
        int ok = 1;
#pragma unroll
        for (int k = 0; k < 16; k++) {
            long long v = p[k];
            if (v < 0 || v >= (long long)n) ok = 0;
        }
        g_is64 = ok;
    }
}

// --- per-edge counting: deg over rows + cnt over cols (1 edge / thread) --------
__global__ void k_count(const void* __restrict__ ei, int n_edges) {
    int e = blockIdx.x * blockDim.x + threadIdx.x;
    if (e < n_edges) {
        int is64 = g_is64;
        atomicAdd(&g_deg[load_idx(ei, 0, e, n_edges, is64)], 1);
        atomicAdd(&g_cnt[load_idx(ei, 1, e, n_edges, is64)], 1);
    }
}

// --- scan phase A: per-block sums of g_cnt; fused g_dis computation -------------
__global__ void k_scanA(int n) {
    __shared__ int warp_sums[SCAN_TPB / 32];
    int tid = threadIdx.x, lane = tid & 31, wid = tid >> 5;
    int base = blockIdx.x * SCAN_PER_BLOCK;
    int s = 0;
#pragma unroll
    for (int k = 0; k < 4; k++) {
        int idx = base + tid + k * SCAN_TPB;
        if (idx < n) {
            s += g_cnt[idx];
            g_dis[idx] = rsqrtf((float)g_deg[idx]);   // fused elementwise pass
        }
    }
#pragma unroll
    for (int d = 16; d > 0; d >>= 1) s += __shfl_down_sync(0xFFFFFFFFu, s, d);
    if (lane == 0) warp_sums[wid] = s;
    __syncthreads();
    if (wid == 0) {
        int v = (lane < SCAN_TPB / 32) ? warp_sums[lane] : 0;
#pragma unroll
        for (int d = 16; d > 0; d >>= 1) v += __shfl_down_sync(0xFFFFFFFFu, v, d);
        if (lane == 0) g_bsum[blockIdx.x] = v;
    }
}

// --- scan phase C: in-block prefix over block sums + local scan; off + cur ------
__global__ void k_scanC(int n) {
    __shared__ int warp_sums[SCAN_TPB / 32];
    __shared__ int s_base;
    int tid = threadIdx.x, lane = tid & 31, wid = tid >> 5;
    int b = blockIdx.x;
    int nblocks = gridDim.x;

    // warp 0: exclusive prefix of block sums up to block b (<=128 sums)
    if (wid == 0) {
        int p = 0, tot = 0;
#pragma unroll
        for (int k = 0; k < 4; k++) {
            int i = lane + k * 32;
            if (i < nblocks) {
                int v = g_bsum[i];
                tot += v;
                if (i < b) p += v;
            }
        }
#pragma unroll
        for (int d = 16; d > 0; d >>= 1) {
            p   += __shfl_down_sync(0xFFFFFFFFu, p, d);
            tot += __shfl_down_sync(0xFFFFFFFFu, tot, d);
        }
        if (lane == 0) {
            s_base = p;
            if (b == nblocks - 1) g_off[n] = tot;   // total edge count
        }
    }

    int base = b * SCAN_PER_BLOCK;
    int idx = base + tid * 4;                  // contiguous 4 per thread
    int v[4];
    int s = 0;
#pragma unroll
    for (int k = 0; k < 4; k++) {
        v[k] = (idx + k < n) ? g_cnt[idx + k] : 0;
        s += v[k];
    }
    int xs = s;
#pragma unroll
    for (int d = 1; d < 32; d <<= 1) {
        int y = __shfl_up_sync(0xFFFFFFFFu, xs, d);
        if (lane >= d) xs += y;
    }
    if (lane == 31) warp_sums[wid] = xs;
    __syncthreads();
    if (wid == 0) {
        int w = (lane < SCAN_TPB / 32) ? warp_sums[lane] : 0;
#pragma unroll
        for (int d = 1; d < 32; d <<= 1) {
            int y = __shfl_up_sync(0xFFFFFFFFu, w, d);
            if (lane >= d) w += y;
        }
        if (lane < SCAN_TPB / 32) warp_sums[lane] = w;
    }
    __syncthreads();
    int warp_excl = (wid == 0) ? 0 : warp_sums[wid - 1];
    int te = s_base + warp_excl + (xs - s);
#pragma unroll
    for (int k = 0; k < 4; k++) {
        if (idx + k < n) {
            g_off[idx + k] = te;
            g_cur[idx + k] = te;   // cursor starts at segment base
        }
        te += v[k];
    }
}

// --- bucket-scatter (src, dis[src]) by destination (1 edge / thread) ------------
// This kernel is atomic-ALU/latency bound, so the extra random dis[r] gather
// rides free here instead of costing L2 bytes in the byte-bound agg kernel.
__global__ void k_scatter(const void* __restrict__ ei, int n_edges) {
    int e = blockIdx.x * blockDim.x + threadIdx.x;
    if (e < n_edges) {
        int is64 = g_is64;
        int r = load_idx(ei, 0, e, n_edges, is64);
        int c = load_idx(ei, 1, e, n_edges, is64);
        float w = g_dis[r];
        int pos = atomicAdd(&g_cur[c], 1);
        g_srcw[pos] = make_uint2((unsigned)r, __float_as_uint(w));
    }
}

// --- warp-per-node aggregation, 2x unrolled, streaming (src,w) payload ----------
__global__ void k_agg(const float2* __restrict__ x, float2* __restrict__ out, int n) {
    int warp = (blockIdx.x * blockDim.x + threadIdx.x) >> 5;
    int lane = threadIdx.x & 31;
    if (warp >= n) return;
    float dc = g_dis[warp];
    float2 xv = x[warp * FEAT2 + lane];
    float w0 = dc * dc;                 // self-loop weight
    float ax = w0 * xv.x, ay = w0 * xv.y;
    float bx = 0.f, by = 0.f;
    int beg = g_off[warp], end = g_off[warp + 1];
    int j = beg;
    for (; j + 2 <= end; j += 2) {
        uint2 e0 = g_srcw[j];
        uint2 e1 = g_srcw[j + 1];
        int r0 = (int)e0.x, r1 = (int)e1.x;
        float wA = dc * __uint_as_float(e0.y);
        float wB = dc * __uint_as_float(e1.y);
        float2 v0 = x[r0 * FEAT2 + lane];
        float2 v1 = x[r1 * FEAT2 + lane];
        ax += wA * v0.x;  ay += wA * v0.y;
        bx += wB * v1.x;  by += wB * v1.y;
    }
    if (j < end) {
        uint2 e0 = g_srcw[j];
        int r0 = (int)e0.x;
        float wA = dc * __uint_as_float(e0.y);
        float2 v0 = x[r0 * FEAT2 + lane];
        ax += wA * v0.x;  ay += wA * v0.y;
    }
    out[warp * FEAT2 + lane] = make_float2(ax + bx, ay + by);
}

extern "C" void kernel_launch(void* const* d_in, const int* in_sizes, int n_in,
                              void* d_out, int out_size) {
    const float* x  = (const float*)d_in[0];
    const void*  ei = d_in[1];
    float* out = (float*)d_out;

    const int n       = in_sizes[0] / FEAT;   // 100000
    const int n_edges = in_sizes[1] / 2;      // 1600000
    const int TPB = 256;
    const int nscan = (n + SCAN_PER_BLOCK - 1) / SCAN_PER_BLOCK;   // 98

    k_init<<<(n + TPB - 1) / TPB, TPB>>>(ei, n);
    k_count<<<(n_edges + TPB - 1) / TPB, TPB>>>(ei, n_edges);
    k_scanA<<<nscan, SCAN_TPB>>>(n);
    k_scanC<<<nscan, SCAN_TPB>>>(n);
    k_scatter<<<(n_edges + TPB - 1) / TPB, TPB>>>(ei, n_edges);

    long long agg_threads = (long long)n * 32;
    k_agg<<<(int)((agg_threads + TPB - 1) / TPB), TPB>>>(
        (const float2*)x, (float2*)out, n);
}